// round 1
// baseline (speedup 1.0000x reference)
#include <cuda_runtime.h>
#include <math.h>

#define NN 50000
#define EE 625000
#define DD 128
#define MEPS 1e-7f
#define AS_STRIDE 132   // padded A-tile stride to kill LDS bank conflicts

// ---------------- device scratch (static: no allocations allowed) -------------
__device__ __align__(16) float g_h [NN * DD];   // current h (layer state)
__device__ __align__(16) float g_h2[NN * DD];   // relu(LN(h)) for next conv
__device__ __align__(16) float g_A [NN * DD];   // (h_in + m) GEMM input
__device__ int g_deg[NN];
__device__ int g_cursor[NN];
__device__ int g_rowptr[NN + 1];
__device__ int g_packed[EE];                    // src(16b) | a0<<16 | a1<<19 | a2<<22

// ---------------- preprocessing ----------------------------------------------
__global__ void k_zero() {
    int i = blockIdx.x * blockDim.x + threadIdx.x;
    if (i < NN) { g_deg[i] = 0; g_cursor[i] = 0; }
}

// AtomEncoder: h0[n,d] = sum_f atom_emb[f, x[n,f], d]
__global__ void k_atom(const int* __restrict__ x, const float* __restrict__ aemb) {
    int i = blockIdx.x * blockDim.x + threadIdx.x;   // over NN*32 float4 slots
    if (i >= NN * 32) return;
    int n = i >> 5, q = i & 31;
    float4 s = make_float4(0.f, 0.f, 0.f, 0.f);
#pragma unroll
    for (int f = 0; f < 9; ++f) {
        int v = x[n * 9 + f];
        float4 t = ((const float4*)(aemb + (f * 64 + v) * DD))[q];
        s.x += t.x; s.y += t.y; s.z += t.z; s.w += t.w;
    }
    ((float4*)(g_h + n * DD))[q] = s;
}

__global__ void k_hist(const int* __restrict__ dst) {
    int e = blockIdx.x * blockDim.x + threadIdx.x;
    if (e < EE) atomicAdd(&g_deg[dst[e]], 1);
}

// single-block exclusive scan of g_deg -> g_rowptr
__global__ void k_scan() {
    __shared__ int ssum[1024];
    const int CH = (NN + 1023) / 1024;
    int tid = threadIdx.x;
    int beg = tid * CH;
    int end = beg + CH; if (end > NN) end = NN;
    int s = 0;
    for (int i = beg; i < end; ++i) s += g_deg[i];
    ssum[tid] = s;
    __syncthreads();
    for (int o = 1; o < 1024; o <<= 1) {
        int v = (tid >= o) ? ssum[tid - o] : 0;
        __syncthreads();
        ssum[tid] += v;
        __syncthreads();
    }
    int run = ssum[tid] - s;   // exclusive prefix
    for (int i = beg; i < end; ++i) { run += g_deg[i]; g_rowptr[i + 1] = run; }
    if (tid == 0) g_rowptr[0] = 0;
}

__global__ void k_scatter(const int* __restrict__ src, const int* __restrict__ dst,
                          const int* __restrict__ ea) {
    int e = blockIdx.x * blockDim.x + threadIdx.x;
    if (e >= EE) return;
    int d = dst[e];
    int pos = atomicAdd(&g_cursor[d], 1);
    int p = src[e] | (ea[e * 3] << 16) | (ea[e * 3 + 1] << 19) | (ea[e * 3 + 2] << 22);
    g_packed[g_rowptr[d] + pos] = p;
}

// ---------------- per-layer aggregation (warp per node, CSR, no atomics) -----
// hin selected by flag: 0 -> g_h (layer 0), 1 -> g_h2
__global__ void __launch_bounds__(256) k_agg(int use_h2, const float* __restrict__ bemb) {
    __shared__ float sb[3 * 8 * DD];       // bond embedding tables, 12 KB
    for (int i = threadIdx.x; i < 3 * 8 * DD; i += 256) sb[i] = bemb[i];
    __syncthreads();

    const float* __restrict__ hin = use_h2 ? g_h2 : g_h;
    int warp = threadIdx.x >> 5, lane = threadIdx.x & 31;
    int n = blockIdx.x * 8 + warp;
    if (n >= NN) return;
    int beg = g_rowptr[n], end = g_rowptr[n + 1];

    float4 mx = make_float4(0.f, 0.f, 0.f, 0.f);   // all msgs > 0, matches ref semantics
    for (int i = beg; i < end; ++i) {
        int p = __ldg(&g_packed[i]);
        const float4 hv = ((const float4*)(hin + (p & 0xFFFF) * DD))[lane];
        const float4 b0 = ((const float4*)(sb +            ((p >> 16) & 7) * DD))[lane];
        const float4 b1 = ((const float4*)(sb + 8  * DD + ((p >> 19) & 7) * DD))[lane];
        const float4 b2 = ((const float4*)(sb + 16 * DD + ((p >> 22) & 7) * DD))[lane];
        float4 m;
        m.x = fmaxf(hv.x + b0.x + b1.x + b2.x, 0.f) + MEPS;
        m.y = fmaxf(hv.y + b0.y + b1.y + b2.y, 0.f) + MEPS;
        m.z = fmaxf(hv.z + b0.z + b1.z + b2.z, 0.f) + MEPS;
        m.w = fmaxf(hv.w + b0.w + b1.w + b2.w, 0.f) + MEPS;
        mx.x = fmaxf(mx.x, m.x); mx.y = fmaxf(mx.y, m.y);
        mx.z = fmaxf(mx.z, m.z); mx.w = fmaxf(mx.w, m.w);
    }

    float4 den = make_float4(0.f, 0.f, 0.f, 0.f);
    float4 num = make_float4(0.f, 0.f, 0.f, 0.f);
    for (int i = beg; i < end; ++i) {
        int p = __ldg(&g_packed[i]);
        const float4 hv = ((const float4*)(hin + (p & 0xFFFF) * DD))[lane];
        const float4 b0 = ((const float4*)(sb +            ((p >> 16) & 7) * DD))[lane];
        const float4 b1 = ((const float4*)(sb + 8  * DD + ((p >> 19) & 7) * DD))[lane];
        const float4 b2 = ((const float4*)(sb + 16 * DD + ((p >> 22) & 7) * DD))[lane];
        float4 m;
        m.x = fmaxf(hv.x + b0.x + b1.x + b2.x, 0.f) + MEPS;
        m.y = fmaxf(hv.y + b0.y + b1.y + b2.y, 0.f) + MEPS;
        m.z = fmaxf(hv.z + b0.z + b1.z + b2.z, 0.f) + MEPS;
        m.w = fmaxf(hv.w + b0.w + b1.w + b2.w, 0.f) + MEPS;
        float ex;
        ex = __expf(m.x - mx.x); den.x += ex; num.x += ex * m.x;
        ex = __expf(m.y - mx.y); den.y += ex; num.y += ex * m.y;
        ex = __expf(m.z - mx.z); den.z += ex; num.z += ex * m.z;
        ex = __expf(m.w - mx.w); den.w += ex; num.w += ex * m.w;
    }

    float4 hn = ((const float4*)(hin + n * DD))[lane];
    float4 o;
    o.x = hn.x + num.x / (den.x + 1e-16f);
    o.y = hn.y + num.y / (den.y + 1e-16f);
    o.z = hn.z + num.z / (den.z + 1e-16f);
    o.w = hn.w + num.w / (den.w + 1e-16f);
    ((float4*)(g_A + n * DD))[lane] = o;
}

// ---------------- GEMM + bias + residual + LN(+ReLU) epilogue ----------------
// hnew = g_A @ W + b [+ g_h];  if !FINAL: g_h = hnew, g_h2 = relu(LN(hnew))
//                              if  FINAL: dout = LN(hnew)
template <bool RES, bool FINAL>
__global__ void __launch_bounds__(256) k_gemm(const float* __restrict__ Wl,
                                              const float* __restrict__ bl,
                                              const float* __restrict__ gl,
                                              const float* __restrict__ btl,
                                              float* __restrict__ dout) {
    extern __shared__ float sm[];
    float* Ws = sm;                       // 128x128
    float* As = sm + DD * DD;             // 64 x AS_STRIDE
    int tid = threadIdx.x;
    int row0 = blockIdx.x * 64;

    for (int i = tid; i < DD * DD / 4; i += 256)
        ((float4*)Ws)[i] = ((const float4*)Wl)[i];
    for (int i = tid; i < 64 * 32; i += 256) {
        int r = i >> 5, q = i & 31;
        int grow = row0 + r;
        float4 v = (grow < NN) ? ((const float4*)(g_A + grow * DD))[q]
                               : make_float4(0.f, 0.f, 0.f, 0.f);
        ((float4*)(As + r * AS_STRIDE))[q] = v;
    }
    __syncthreads();

    int tx = tid & 15, ty = tid >> 4;     // tx: 8 cols, ty: 4 rows
    float acc[4][8];
#pragma unroll
    for (int r = 0; r < 4; ++r)
#pragma unroll
        for (int j = 0; j < 8; ++j) acc[r][j] = 0.f;

#pragma unroll 8
    for (int k = 0; k < DD; ++k) {
        float a[4];
#pragma unroll
        for (int r = 0; r < 4; ++r) a[r] = As[(ty * 4 + r) * AS_STRIDE + k];
        float4 w0 = ((const float4*)(Ws + k * DD))[tx * 2];
        float4 w1 = ((const float4*)(Ws + k * DD))[tx * 2 + 1];
        float w[8] = {w0.x, w0.y, w0.z, w0.w, w1.x, w1.y, w1.z, w1.w};
#pragma unroll
        for (int r = 0; r < 4; ++r)
#pragma unroll
            for (int j = 0; j < 8; ++j) acc[r][j] += a[r] * w[j];
    }

    // epilogue
    float4 bA = ((const float4*)(bl))[tx * 2], bB = ((const float4*)(bl))[tx * 2 + 1];
    float4 gA = ((const float4*)(gl))[tx * 2], gB = ((const float4*)(gl))[tx * 2 + 1];
    float4 tA = ((const float4*)(btl))[tx * 2], tB = ((const float4*)(btl))[tx * 2 + 1];
    float bb[8] = {bA.x, bA.y, bA.z, bA.w, bB.x, bB.y, bB.z, bB.w};
    float gg[8] = {gA.x, gA.y, gA.z, gA.w, gB.x, gB.y, gB.z, gB.w};
    float tt[8] = {tA.x, tA.y, tA.z, tA.w, tB.x, tB.y, tB.z, tB.w};

#pragma unroll
    for (int r = 0; r < 4; ++r) {
        int row = row0 + ty * 4 + r;
        int rowc = (row < NN) ? row : (NN - 1);   // clamp loads, keep warp converged
        float v[8];
#pragma unroll
        for (int j = 0; j < 8; ++j) v[j] = acc[r][j] + bb[j];
        if (RES) {
            float4 r0 = ((const float4*)(g_h + rowc * DD + tx * 8))[0];
            float4 r1 = ((const float4*)(g_h + rowc * DD + tx * 8))[1];
            v[0] += r0.x; v[1] += r0.y; v[2] += r0.z; v[3] += r0.w;
            v[4] += r1.x; v[5] += r1.y; v[6] += r1.z; v[7] += r1.w;
        }
        float s = 0.f, s2 = 0.f;
#pragma unroll
        for (int j = 0; j < 8; ++j) { s += v[j]; s2 += v[j] * v[j]; }
#pragma unroll
        for (int o = 8; o >= 1; o >>= 1) {
            s  += __shfl_xor_sync(0xffffffffu, s,  o, 16);
            s2 += __shfl_xor_sync(0xffffffffu, s2, o, 16);
        }
        float mu  = s * (1.f / 128.f);
        float var = s2 * (1.f / 128.f) - mu * mu;
        float rs  = rsqrtf(var + 1e-5f);
        float y[8];
#pragma unroll
        for (int j = 0; j < 8; ++j) y[j] = (v[j] - mu) * rs * gg[j] + tt[j];

        if (row < NN) {
            if (FINAL) {
                ((float4*)(dout + row * DD + tx * 8))[0] = make_float4(y[0], y[1], y[2], y[3]);
                ((float4*)(dout + row * DD + tx * 8))[1] = make_float4(y[4], y[5], y[6], y[7]);
            } else {
                ((float4*)(g_h + row * DD + tx * 8))[0] = make_float4(v[0], v[1], v[2], v[3]);
                ((float4*)(g_h + row * DD + tx * 8))[1] = make_float4(v[4], v[5], v[6], v[7]);
                float r0 = fmaxf(y[0], 0.f), r1 = fmaxf(y[1], 0.f), r2 = fmaxf(y[2], 0.f), r3 = fmaxf(y[3], 0.f);
                float r4 = fmaxf(y[4], 0.f), r5 = fmaxf(y[5], 0.f), r6 = fmaxf(y[6], 0.f), r7 = fmaxf(y[7], 0.f);
                ((float4*)(g_h2 + row * DD + tx * 8))[0] = make_float4(r0, r1, r2, r3);
                ((float4*)(g_h2 + row * DD + tx * 8))[1] = make_float4(r4, r5, r6, r7);
            }
        }
    }
}

// ---------------- launch ------------------------------------------------------
extern "C" void kernel_launch(void* const* d_in, const int* in_sizes, int n_in,
                              void* d_out, int out_size) {
    const int*   x    = (const int*)  d_in[0];
    const int*   ei   = (const int*)  d_in[1];
    const int*   ea   = (const int*)  d_in[2];
    const float* aemb = (const float*)d_in[3];
    const float* bemb = (const float*)d_in[4];
    const float* W    = (const float*)d_in[5];
    const float* b    = (const float*)d_in[6];
    const float* g    = (const float*)d_in[7];
    const float* bt   = (const float*)d_in[8];
    float* out = (float*)d_out;
    const int* src = ei;
    const int* dst = ei + EE;

    const int SMEM = (DD * DD + 64 * AS_STRIDE) * (int)sizeof(float);  // ~97.5 KB
    cudaFuncSetAttribute((const void*)k_gemm<false, false>, cudaFuncAttributeMaxDynamicSharedMemorySize, SMEM);
    cudaFuncSetAttribute((const void*)k_gemm<true,  false>, cudaFuncAttributeMaxDynamicSharedMemorySize, SMEM);
    cudaFuncSetAttribute((const void*)k_gemm<true,  true >, cudaFuncAttributeMaxDynamicSharedMemorySize, SMEM);

    k_zero<<<(NN + 255) / 256, 256>>>();
    k_atom<<<(NN * 32 + 255) / 256, 256>>>(x, aemb);
    k_hist<<<(EE + 255) / 256, 256>>>(dst);
    k_scan<<<1, 1024>>>();
    k_scatter<<<(EE + 255) / 256, 256>>>(src, dst, ea);

    int gemm_blocks = (NN + 63) / 64;
    for (int l = 0; l < 7; ++l) {
        k_agg<<<(NN + 7) / 8, 256>>>(l == 0 ? 0 : 1, bemb);
        const float* Wl  = W  + l * DD * DD;
        const float* bl  = b  + l * DD;
        const float* gl  = g  + l * DD;
        const float* btl = bt + l * DD;
        if (l == 0)
            k_gemm<false, false><<<gemm_blocks, 256, SMEM>>>(Wl, bl, gl, btl, out);
        else if (l < 6)
            k_gemm<true, false><<<gemm_blocks, 256, SMEM>>>(Wl, bl, gl, btl, out);
        else
            k_gemm<true, true><<<gemm_blocks, 256, SMEM>>>(Wl, bl, gl, btl, out);
    }
}

// round 2
// speedup vs baseline: 1.3029x; 1.3029x over previous
#include <cuda_runtime.h>
#include <math.h>

#define NN 50000
#define EE 625000
#define DD 128
#define MEPS 1e-7f
#define AS_STRIDE 132   // padded A-tile stride (floats)

// ---------------- device scratch (static: no allocations allowed) -------------
__device__ __align__(16) float g_h [NN * DD];   // current h (layer state)
__device__ __align__(16) float g_h2[NN * DD];   // relu(LN(h)) for next conv
__device__ __align__(16) float g_A [NN * DD];   // (h_in + m) GEMM input
__device__ int g_deg[NN];
__device__ int g_cursor[NN];
__device__ int g_start[NN];
__device__ int g_total;
__device__ int g_packed[EE];                    // src(16b) | a0<<16 | a1<<19 | a2<<22

// packed f32x2 FMA: d.lo += a.lo*b.lo ; d.hi += a.hi*b.hi  (sm_103a)
__device__ __forceinline__ void ffma2(float2& d, const float2& a, const float2& b) {
    asm("fma.rn.f32x2 %0, %1, %2, %0;"
        : "+l"(*reinterpret_cast<unsigned long long*>(&d))
        : "l"(*reinterpret_cast<const unsigned long long*>(&a)),
          "l"(*reinterpret_cast<const unsigned long long*>(&b)));
}

// ---------------- preprocessing ----------------------------------------------
// AtomEncoder + zero-init of counters (zero must precede k_hist; stream order ok)
__global__ void k_atom(const int* __restrict__ x, const float* __restrict__ aemb) {
    int i = blockIdx.x * blockDim.x + threadIdx.x;   // over NN*32 float4 slots
    if (i >= NN * 32) return;
    int n = i >> 5, q = i & 31;
    if (q == 0) { g_deg[n] = 0; g_cursor[n] = 0; if (n == 0) g_total = 0; }
    float4 s = make_float4(0.f, 0.f, 0.f, 0.f);
#pragma unroll
    for (int f = 0; f < 9; ++f) {
        int v = x[n * 9 + f];
        float4 t = ((const float4*)(aemb + (f * 64 + v) * DD))[q];
        s.x += t.x; s.y += t.y; s.z += t.z; s.w += t.w;
    }
    ((float4*)(g_h + n * DD))[q] = s;
}

__global__ void k_hist(const int* __restrict__ dst) {
    int e = blockIdx.x * blockDim.x + threadIdx.x;
    if (e < EE) atomicAdd(&g_deg[dst[e]], 1);
}

// assign contiguous (unordered) segment starts: warp-scan + 1 atomic per warp
__global__ void k_start() {
    int i = blockIdx.x * blockDim.x + threadIdx.x;
    int lane = threadIdx.x & 31;
    int d = (i < NN) ? g_deg[i] : 0;
    int s = d;
#pragma unroll
    for (int o = 1; o < 32; o <<= 1) {
        int v = __shfl_up_sync(0xffffffffu, s, o);
        if (lane >= o) s += v;
    }
    int warpsum = __shfl_sync(0xffffffffu, s, 31);
    int base = 0;
    if (lane == 31) base = atomicAdd(&g_total, warpsum);
    base = __shfl_sync(0xffffffffu, base, 31);
    if (i < NN) g_start[i] = base + s - d;
}

__global__ void k_scatter(const int* __restrict__ src, const int* __restrict__ dst,
                          const int* __restrict__ ea) {
    int e = blockIdx.x * blockDim.x + threadIdx.x;
    if (e >= EE) return;
    int d = dst[e];
    int pos = atomicAdd(&g_cursor[d], 1);
    int p = src[e] | (ea[e * 3] << 16) | (ea[e * 3 + 1] << 19) | (ea[e * 3 + 2] << 22);
    g_packed[g_start[d] + pos] = p;
}

// ---------------- per-layer aggregation: SINGLE PASS, no max shift -----------
// exp without max-subtraction is exact here: msgs in (1e-7, ~5], shift cancels.
__global__ void __launch_bounds__(256) k_agg(int use_h2, const float* __restrict__ bemb) {
    __shared__ float sb[3 * 8 * DD];       // bond embedding tables, 12 KB
    for (int i = threadIdx.x; i < 3 * 8 * DD; i += 256) sb[i] = bemb[i];
    __syncthreads();

    const float* __restrict__ hin = use_h2 ? g_h2 : g_h;
    int warp = threadIdx.x >> 5, lane = threadIdx.x & 31;
    int n = blockIdx.x * 8 + warp;
    if (n >= NN) return;
    int beg = g_start[n], end = beg + g_deg[n];

    float4 den = make_float4(0.f, 0.f, 0.f, 0.f);
    float4 num = make_float4(0.f, 0.f, 0.f, 0.f);
    for (int i = beg; i < end; ++i) {
        int p = __ldg(&g_packed[i]);
        const float4 hv = ((const float4*)(hin + (p & 0xFFFF) * DD))[lane];
        const float4 b0 = ((const float4*)(sb +           ((p >> 16) & 7) * DD))[lane];
        const float4 b1 = ((const float4*)(sb + 8  * DD + ((p >> 19) & 7) * DD))[lane];
        const float4 b2 = ((const float4*)(sb + 16 * DD + ((p >> 22) & 7) * DD))[lane];
        float4 m;
        m.x = fmaxf(hv.x + b0.x + b1.x + b2.x, 0.f) + MEPS;
        m.y = fmaxf(hv.y + b0.y + b1.y + b2.y, 0.f) + MEPS;
        m.z = fmaxf(hv.z + b0.z + b1.z + b2.z, 0.f) + MEPS;
        m.w = fmaxf(hv.w + b0.w + b1.w + b2.w, 0.f) + MEPS;
        float ex;
        ex = __expf(m.x); den.x += ex; num.x += ex * m.x;
        ex = __expf(m.y); den.y += ex; num.y += ex * m.y;
        ex = __expf(m.z); den.z += ex; num.z += ex * m.z;
        ex = __expf(m.w); den.w += ex; num.w += ex * m.w;
    }

    float4 hn = ((const float4*)(hin + n * DD))[lane];
    float4 o;
    o.x = hn.x + num.x / (den.x + 1e-16f);
    o.y = hn.y + num.y / (den.y + 1e-16f);
    o.z = hn.z + num.z / (den.z + 1e-16f);
    o.w = hn.w + num.w / (den.w + 1e-16f);
    ((float4*)(g_A + n * DD))[lane] = o;
}

// ---------------- GEMM (f32x2) + bias + residual + LN(+ReLU) epilogue --------
// 128-row tiles, 512 threads. hnew = g_A @ W + b [+ g_h]
// !FINAL: g_h=hnew, g_h2=relu(LN(hnew));  FINAL: dout=LN(hnew)
template <bool RES, bool FINAL>
__global__ void __launch_bounds__(512) k_gemm(const float* __restrict__ Wl,
                                              const float* __restrict__ bl,
                                              const float* __restrict__ gl,
                                              const float* __restrict__ btl,
                                              float* __restrict__ dout) {
    extern __shared__ float sm[];
    float* Ws = sm;                       // 128x128
    float* As = sm + DD * DD;             // 128 x AS_STRIDE
    int tid = threadIdx.x;
    int row0 = blockIdx.x * 128;

    for (int i = tid; i < DD * DD / 4; i += 512)
        ((float4*)Ws)[i] = ((const float4*)Wl)[i];
    for (int i = tid; i < 128 * 32; i += 512) {
        int r = i >> 5, q = i & 31;
        int grow = row0 + r;
        float4 v = (grow < NN) ? ((const float4*)(g_A + grow * DD))[q]
                               : make_float4(0.f, 0.f, 0.f, 0.f);
        ((float4*)(As + r * AS_STRIDE))[q] = v;
    }
    __syncthreads();

    int tx = tid & 15, ty = tid >> 4;     // tx: 8 cols (4 f32x2 pairs), ty: 4 rows
    float2 acc[4][4];
#pragma unroll
    for (int r = 0; r < 4; ++r)
#pragma unroll
        for (int j = 0; j < 4; ++j) acc[r][j] = make_float2(0.f, 0.f);

#pragma unroll 2
    for (int k0 = 0; k0 < DD; k0 += 4) {
        float4 a4[4];
#pragma unroll
        for (int r = 0; r < 4; ++r)
            a4[r] = *(const float4*)&As[(ty * 4 + r) * AS_STRIDE + k0];
#pragma unroll
        for (int kk = 0; kk < 4; ++kk) {
            int k = k0 + kk;
            float4 w0 = ((const float4*)(Ws + k * DD))[tx * 2];
            float4 w1 = ((const float4*)(Ws + k * DD))[tx * 2 + 1];
            float2 wp[4] = {{w0.x, w0.y}, {w0.z, w0.w}, {w1.x, w1.y}, {w1.z, w1.w}};
#pragma unroll
            for (int r = 0; r < 4; ++r) {
                float av = (kk == 0) ? a4[r].x : (kk == 1) ? a4[r].y
                         : (kk == 2) ? a4[r].z : a4[r].w;
                float2 ap = make_float2(av, av);
#pragma unroll
                for (int j = 0; j < 4; ++j) ffma2(acc[r][j], ap, wp[j]);
            }
        }
    }

    // epilogue
    float4 bA = ((const float4*)(bl))[tx * 2], bB = ((const float4*)(bl))[tx * 2 + 1];
    float4 gA = ((const float4*)(gl))[tx * 2], gB = ((const float4*)(gl))[tx * 2 + 1];
    float4 tA = ((const float4*)(btl))[tx * 2], tB = ((const float4*)(btl))[tx * 2 + 1];
    float bb[8] = {bA.x, bA.y, bA.z, bA.w, bB.x, bB.y, bB.z, bB.w};
    float gg[8] = {gA.x, gA.y, gA.z, gA.w, gB.x, gB.y, gB.z, gB.w};
    float tt[8] = {tA.x, tA.y, tA.z, tA.w, tB.x, tB.y, tB.z, tB.w};

#pragma unroll
    for (int r = 0; r < 4; ++r) {
        int row = row0 + ty * 4 + r;
        int rowc = (row < NN) ? row : (NN - 1);   // clamp loads, keep warp converged
        float v[8];
#pragma unroll
        for (int j = 0; j < 4; ++j) { v[2 * j] = acc[r][j].x + bb[2 * j]; v[2 * j + 1] = acc[r][j].y + bb[2 * j + 1]; }
        if (RES) {
            float4 r0 = ((const float4*)(g_h + rowc * DD + tx * 8))[0];
            float4 r1 = ((const float4*)(g_h + rowc * DD + tx * 8))[1];
            v[0] += r0.x; v[1] += r0.y; v[2] += r0.z; v[3] += r0.w;
            v[4] += r1.x; v[5] += r1.y; v[6] += r1.z; v[7] += r1.w;
        }
        float s = 0.f, s2 = 0.f;
#pragma unroll
        for (int j = 0; j < 8; ++j) { s += v[j]; s2 += v[j] * v[j]; }
#pragma unroll
        for (int o = 8; o >= 1; o >>= 1) {
            s  += __shfl_xor_sync(0xffffffffu, s,  o, 16);
            s2 += __shfl_xor_sync(0xffffffffu, s2, o, 16);
        }
        float mu  = s * (1.f / 128.f);
        float var = s2 * (1.f / 128.f) - mu * mu;
        float rs  = rsqrtf(var + 1e-5f);
        float y[8];
#pragma unroll
        for (int j = 0; j < 8; ++j) y[j] = (v[j] - mu) * rs * gg[j] + tt[j];

        if (row < NN) {
            if (FINAL) {
                ((float4*)(dout + row * DD + tx * 8))[0] = make_float4(y[0], y[1], y[2], y[3]);
                ((float4*)(dout + row * DD + tx * 8))[1] = make_float4(y[4], y[5], y[6], y[7]);
            } else {
                ((float4*)(g_h + row * DD + tx * 8))[0] = make_float4(v[0], v[1], v[2], v[3]);
                ((float4*)(g_h + row * DD + tx * 8))[1] = make_float4(v[4], v[5], v[6], v[7]);
                ((float4*)(g_h2 + row * DD + tx * 8))[0] =
                    make_float4(fmaxf(y[0], 0.f), fmaxf(y[1], 0.f), fmaxf(y[2], 0.f), fmaxf(y[3], 0.f));
                ((float4*)(g_h2 + row * DD + tx * 8))[1] =
                    make_float4(fmaxf(y[4], 0.f), fmaxf(y[5], 0.f), fmaxf(y[6], 0.f), fmaxf(y[7], 0.f));
            }
        }
    }
}

// ---------------- launch ------------------------------------------------------
extern "C" void kernel_launch(void* const* d_in, const int* in_sizes, int n_in,
                              void* d_out, int out_size) {
    const int*   x    = (const int*)  d_in[0];
    const int*   ei   = (const int*)  d_in[1];
    const int*   ea   = (const int*)  d_in[2];
    const float* aemb = (const float*)d_in[3];
    const float* bemb = (const float*)d_in[4];
    const float* W    = (const float*)d_in[5];
    const float* b    = (const float*)d_in[6];
    const float* g    = (const float*)d_in[7];
    const float* bt   = (const float*)d_in[8];
    float* out = (float*)d_out;
    const int* src = ei;
    const int* dst = ei + EE;

    const int SMEM = (DD * DD + 128 * AS_STRIDE) * (int)sizeof(float);  // 130 KB
    cudaFuncSetAttribute((const void*)k_gemm<false, false>, cudaFuncAttributeMaxDynamicSharedMemorySize, SMEM);
    cudaFuncSetAttribute((const void*)k_gemm<true,  false>, cudaFuncAttributeMaxDynamicSharedMemorySize, SMEM);
    cudaFuncSetAttribute((const void*)k_gemm<true,  true >, cudaFuncAttributeMaxDynamicSharedMemorySize, SMEM);

    k_atom<<<(NN * 32 + 255) / 256, 256>>>(x, aemb);          // launch 0 (+zero init)
    k_hist<<<(EE + 255) / 256, 256>>>(dst);                   // launch 1
    k_start<<<(NN + 255) / 256, 256>>>();                     // launch 2
    k_scatter<<<(EE + 255) / 256, 256>>>(src, dst, ea);       // launch 3

    int gemm_blocks = (NN + 127) / 128;
    for (int l = 0; l < 7; ++l) {
        k_agg<<<(NN + 7) / 8, 256>>>(l == 0 ? 0 : 1, bemb);   // launch 4 = agg0
        const float* Wl  = W  + l * DD * DD;
        const float* bl  = b  + l * DD;
        const float* gl  = g  + l * DD;
        const float* btl = bt + l * DD;
        if (l == 0)
            k_gemm<false, false><<<gemm_blocks, 512, SMEM>>>(Wl, bl, gl, btl, out);  // launch 5 (profiled)
        else if (l < 6)
            k_gemm<true, false><<<gemm_blocks, 512, SMEM>>>(Wl, bl, gl, btl, out);
        else
            k_gemm<true, true><<<gemm_blocks, 512, SMEM>>>(Wl, bl, gl, btl, out);
    }
}